// round 1
// baseline (speedup 1.0000x reference)
#include <cuda_runtime.h>
#include <stdint.h>

// Problem constants
#define BINSD   512
#define BATCH   64
#define NPTS    4096
#define CELLS   (BATCH * BINSD * BINSD)      // 16,777,216 cells
#define NPOINTS (BATCH * NPTS)               // 262,144 points

// Per-cell winner token: 0 = empty, else (n+1) of the winning point.
// __device__ globals are zero-initialized at module load; the resolve kernel
// self-cleans every touched cell back to 0, so every launch starts from the
// same state (deterministic, graph-replay safe).
static __device__ unsigned int g_winner[CELLS];

// ---------------------------------------------------------------------------
// Kernel 1: background fill. One float4 (16B) per cell.
// out[b,i,j] = {0.63, 0.63, j/512, i/512}
// ---------------------------------------------------------------------------
__global__ void __launch_bounds__(256) fill_kernel(float4* __restrict__ out) {
    int idx = blockIdx.x * blockDim.x + threadIdx.x;   // 0 .. CELLS-1 (exact grid)
    const float inv = 1.0f / (float)BINSD;
    int j = idx & (BINSD - 1);
    int i = (idx >> 9) & (BINSD - 1);
    out[idx] = make_float4(0.63f, 0.63f, (float)j * inv, (float)i * inv);
}

// ---------------------------------------------------------------------------
// Kernel 2: per-point atomicMax of token (n+1) into its cell.
// ---------------------------------------------------------------------------
__global__ void __launch_bounds__(256) scatter_max_kernel(
    const float2* __restrict__ pts) {
    int t = blockIdx.x * blockDim.x + threadIdx.x;     // 0 .. NPOINTS-1
    float2 p = pts[t];
    int b = t >> 12;                 // /NPTS
    unsigned int tok = (unsigned int)(t & (NPTS - 1)) + 1u;
    // x/delta with delta = 1/512 (exact power of two) == x*512.0f bit-exactly;
    // truncation matches astype(int32) for non-negative inputs.
    int row = (int)(p.x * 512.0f);
    int col = (int)(p.y * 512.0f);
    int cell = (b << 18) | (row << 9) | col;
    atomicMax(&g_winner[cell], tok);
}

// ---------------------------------------------------------------------------
// Kernel 3: the winning point writes its cell and resets the token to 0.
// Losers read either the winner's token (!= theirs) or 0 — both are no-ops,
// so the reset racing with loser reads is safe (tokens are >= 1).
// ---------------------------------------------------------------------------
__global__ void __launch_bounds__(256) resolve_kernel(
    const float2* __restrict__ pts, float4* __restrict__ out) {
    int t = blockIdx.x * blockDim.x + threadIdx.x;     // 0 .. NPOINTS-1
    float2 p = pts[t];
    int b = t >> 12;
    unsigned int tok = (unsigned int)(t & (NPTS - 1)) + 1u;
    int row = (int)(p.x * 512.0f);
    int col = (int)(p.y * 512.0f);
    int cell = (b << 18) | (row << 9) | col;
    if (g_winner[cell] == tok) {
        out[cell] = make_float4(1.0f, 1.0f, p.x, p.y);
        g_winner[cell] = 0u;   // self-clean for the next launch
    }
}

extern "C" void kernel_launch(void* const* d_in, const int* in_sizes, int n_in,
                              void* d_out, int out_size) {
    const float2* pts = (const float2*)d_in[0];   // batch [64, 4096, 2] fp32
    float4* out = (float4*)d_out;                 // [64, 512, 512, 4] fp32

    fill_kernel<<<CELLS / 256, 256>>>(out);
    scatter_max_kernel<<<NPOINTS / 256, 256>>>(pts);
    resolve_kernel<<<NPOINTS / 256, 256>>>(pts, out);
}

// round 2
// speedup vs baseline: 1.0303x; 1.0303x over previous
#include <cuda_runtime.h>
#include <stdint.h>

// Problem constants
#define BINSD   512
#define BATCH   64
#define NPTS    4096
#define CELLS   (BATCH * BINSD * BINSD)      // 16,777,216 cells
#define NPOINTS (BATCH * NPTS)               // 262,144 points

#define SCAT_BLOCKS 256                      // 256 blk * 256 thr * 4 pts = 262,144
#define FILL_BLOCKS 16384                    // 16384 blk * 256 thr * 4 cells = 16,777,216

// Per-cell winner token: 0 = empty, else (n+1) of the winning point within the
// batch. Zero-initialized at module load; resolve self-cleans every touched
// cell back to 0, so every graph replay starts from identical state.
static __device__ unsigned int g_winner[CELLS];

// ---------------------------------------------------------------------------
// Fused kernel: low block indices (scheduled first) run the point scatter
// (atomicMax of token into g_winner) concurrently with the DRAM-bound
// background fill done by the remaining blocks. Scatter is fully hidden.
// ---------------------------------------------------------------------------
__global__ void __launch_bounds__(256) fused_fill_scatter_kernel(
    float4* __restrict__ out, const float4* __restrict__ pts4) {
    unsigned bid = blockIdx.x;

    if (bid < SCAT_BLOCKS) {
        // ---- scatter: 4 points per thread via two float4 loads ----
        int t0 = (bid * 256 + threadIdx.x) * 4;        // first point index
        float4 a = pts4[t0 >> 1];                      // points t0, t0+1
        float4 b = pts4[(t0 >> 1) + 1];                // points t0+2, t0+3
        int batch = t0 >> 12;                          // 4 points never cross a batch (4096%4==0)
        int cellbase = batch << 18;

        float px[4] = {a.x, a.z, b.x, b.z};
        float py[4] = {a.y, a.w, b.y, b.w};
        #pragma unroll
        for (int k = 0; k < 4; k++) {
            // delta = 1/512 exactly, so x/delta == x*512.0f bit-exactly;
            // truncation matches astype(int32) for non-negative inputs.
            int row = (int)(px[k] * 512.0f);
            int col = (int)(py[k] * 512.0f);
            unsigned int tok = (unsigned int)((t0 + k) & (NPTS - 1)) + 1u;
            atomicMax(&g_winner[cellbase | (row << 9) | col], tok);
        }
    } else {
        // ---- fill: 4 per-instruction-coalesced float4 stores per thread ----
        int fb = bid - SCAT_BLOCKS;
        int base = fb * 1024 + threadIdx.x;            // float4-element units
        const float inv = 1.0f / (float)BINSD;
        #pragma unroll
        for (int k = 0; k < 4; k++) {
            int idx = base + k * 256;
            int j = idx & (BINSD - 1);
            int i = (idx >> 9) & (BINSD - 1);
            out[idx] = make_float4(0.63f, 0.63f, (float)j * inv, (float)i * inv);
        }
    }
}

// ---------------------------------------------------------------------------
// Resolve: the winning point overwrites its cell and resets the token to 0.
// Losers read either the winner's token (!= theirs) or 0 — both no-ops, so
// the reset racing with loser reads is safe (tokens are >= 1).
// ---------------------------------------------------------------------------
__global__ void __launch_bounds__(256) resolve_kernel(
    const float2* __restrict__ pts, float4* __restrict__ out) {
    int t = blockIdx.x * blockDim.x + threadIdx.x;     // 0 .. NPOINTS-1
    float2 p = __ldg(&pts[t]);
    int b = t >> 12;
    unsigned int tok = (unsigned int)(t & (NPTS - 1)) + 1u;
    int row = (int)(p.x * 512.0f);
    int col = (int)(p.y * 512.0f);
    int cell = (b << 18) | (row << 9) | col;
    if (g_winner[cell] == tok) {
        out[cell] = make_float4(1.0f, 1.0f, p.x, p.y);
        g_winner[cell] = 0u;   // self-clean for the next replay
    }
}

extern "C" void kernel_launch(void* const* d_in, const int* in_sizes, int n_in,
                              void* d_out, int out_size) {
    const float2* pts = (const float2*)d_in[0];   // batch [64, 4096, 2] fp32
    float4* out = (float4*)d_out;                 // [64, 512, 512, 4] fp32

    fused_fill_scatter_kernel<<<SCAT_BLOCKS + FILL_BLOCKS, 256>>>(
        out, (const float4*)pts);
    resolve_kernel<<<NPOINTS / 256, 256>>>(pts, out);
}